// round 4
// baseline (speedup 1.0000x reference)
#include <cuda_runtime.h>
#include <cuda_bf16.h>
#include <cstdint>

// Problem constants
#define B_      16
#define CIN     128
#define COUT    128
#define H_      128
#define W_      128
#define S_      512
#define EPS_    1e-8f

// Tiling
#define TCO 32   // co per block
#define TH  16   // h per block
#define TW  16   // w per block
#define TCI 8    // ci chunk

// Scratch (tiny): modulation scales + demod coefs
__device__ float g_s[B_ * CIN];          // s[b][ci]
__device__ float g_w2[COUT * CIN];       // sum_k weight^2
__device__ float g_decoef[B_ * COUT];    // rsqrt(...)

// ---- packed f32x2 helpers (sm_103a) --------------------------------------
__device__ __forceinline__ void ffma2(uint64_t& d, uint64_t a, uint64_t b) {
    asm("fma.rn.f32x2 %0, %1, %2, %0;" : "+l"(d) : "l"(a), "l"(b));
}
__device__ __forceinline__ uint64_t pack2(float lo, float hi) {
    uint64_t r;
    asm("mov.b64 %0, {%1, %2};" : "=l"(r) : "f"(lo), "f"(hi));
    return r;
}
__device__ __forceinline__ void unpack2(uint64_t v, float& lo, float& hi) {
    asm("mov.b64 {%0, %1}, %2;" : "=f"(lo), "=f"(hi) : "l"(v));
}

// ---------------------------------------------------------------------------
// Kernel 1: s[b][ci] = style[b] . mod_w[ci] + mod_b[ci]
__global__ void k_style(const float* __restrict__ style,
                        const float* __restrict__ mod_w,
                        const float* __restrict__ mod_b) {
    int b = blockIdx.x;
    int ci = threadIdx.x;
    const float* st = style + b * S_;
    const float* mw = mod_w + ci * S_;
    float acc = 0.f;
#pragma unroll 8
    for (int k = 0; k < S_; k++) acc = fmaf(st[k], mw[k], acc);
    g_s[b * CIN + ci] = acc + mod_b[ci];
}

// ---------------------------------------------------------------------------
// Kernel 2: W2[co][ci] = sum_k weight[co][ci][k]^2
__global__ void k_w2(const float* __restrict__ weight) {
    int i = blockIdx.x * blockDim.x + threadIdx.x;  // co*CIN + ci
    if (i >= COUT * CIN) return;
    const float* w = weight + i * 9;
    float acc = 0.f;
#pragma unroll
    for (int k = 0; k < 9; k++) acc = fmaf(w[k], w[k], acc);
    g_w2[i] = acc;
}

// ---------------------------------------------------------------------------
// Kernel 3: decoef[b][co] = rsqrt(sum_ci W2[co][ci]*s[b][ci]^2 + eps)
__global__ void k_decoef() {
    int i = blockIdx.x * blockDim.x + threadIdx.x;  // b*COUT + co
    if (i >= B_ * COUT) return;
    int b = i / COUT;
    int co = i % COUT;
    const float* w2 = g_w2 + co * CIN;
    const float* sb = g_s + b * CIN;
    float acc = 0.f;
#pragma unroll 8
    for (int ci = 0; ci < CIN; ci++) {
        float sv = sb[ci];
        acc = fmaf(w2[ci], sv * sv, acc);
    }
    g_decoef[i] = rsqrtf(acc + EPS_);
}

// ---------------------------------------------------------------------------
// Main conv (packed f32x2 mainloop):
//   out[b,co,h,w] = decoef[b,co] * sum_{ci,kh,kw} (x[b,ci,h+kh-1,w+kw-1]*s[b,ci]) * weight[co,ci,kh,kw]
//
// grid: (W_/TW, H_/TH, B_ * COUT/TCO), block: 256 threads
// thread: tg = tid>>6 (8-co group), th = (tid>>2)&15 (row), tw = tid&3.
// Each thread computes 8 co x 4 w (w = tw + 4*j), held as 8 x 2 f32x2 pairs.
// smem bank check (x loads): addr = (th+kh)*20 + tw + 4j + kw; within a warp
// th in 0..7 -> th*20 mod 32 = {0,20,8,28,16,4,24,12}, +tw(0..3) -> 32 distinct
// banks, conflict-free. Weight LDS.64 is warp-uniform -> broadcast.
__global__ void __launch_bounds__(256)
k_conv(const float* __restrict__ x,
       const float* __restrict__ weight,
       float* __restrict__ out) {
    __shared__ float  xs[TCI][TH + 2][20];        // input patch, scaled by s
    __shared__ float2 ws[TCI][TCO][10];           // weights, duplicated (w,w)

    const int b   = blockIdx.z >> 2;
    const int co0 = (blockIdx.z & 3) * TCO;
    const int h0  = blockIdx.y * TH;
    const int w0  = blockIdx.x * TW;

    const int tid = threadIdx.x;
    const int tg  = tid >> 6;          // 0..3
    const int th  = (tid >> 2) & 15;   // 0..15
    const int tw  = tid & 3;           // 0..3

    const float* sb = g_s + b * CIN;

    uint64_t acc[8][2];
#pragma unroll
    for (int r = 0; r < 8; r++) {
        acc[r][0] = 0ull;
        acc[r][1] = 0ull;
    }

    for (int ci0 = 0; ci0 < CIN; ci0 += TCI) {
        // ---- load input patch (8 x 18 x 18), scaled by s[b][ci] ----
        for (int i = tid; i < TCI * 18 * 18; i += 256) {
            int ci  = i / (18 * 18);
            int rem = i - ci * (18 * 18);
            int hh  = rem / 18;
            int ww  = rem - hh * 18;
            int gh = h0 + hh - 1;
            int gw = w0 + ww - 1;
            float v = 0.f;
            if (gh >= 0 && gh < H_ && gw >= 0 && gw < W_)
                v = x[(((size_t)b * CIN + ci0 + ci) * H_ + gh) * W_ + gw] * sb[ci0 + ci];
            xs[ci][hh][ww] = v;
        }
        // ---- load weights (32 co x 8 ci x 9), duplicated into f32x2 ----
        for (int i = tid; i < TCO * TCI * 9; i += 256) {
            int co  = i / (TCI * 9);
            int rem = i - co * (TCI * 9);
            int ci  = rem / 9;
            int k   = rem - ci * 9;
            float wv = weight[((size_t)(co0 + co) * CIN + ci0 + ci) * 9 + k];
            ws[ci][co][k] = make_float2(wv, wv);
        }
        __syncthreads();

        // ---- compute (packed f32x2) ----
#pragma unroll 2
        for (int ci = 0; ci < TCI; ci++) {
#pragma unroll
            for (int kh = 0; kh < 3; kh++) {
#pragma unroll
                for (int kw = 0; kw < 3; kw++) {
                    float xv0 = xs[ci][th + kh][tw + 0  + kw];
                    float xv1 = xs[ci][th + kh][tw + 4  + kw];
                    float xv2 = xs[ci][th + kh][tw + 8  + kw];
                    float xv3 = xs[ci][th + kh][tw + 12 + kw];
                    uint64_t x01 = pack2(xv0, xv1);
                    uint64_t x23 = pack2(xv2, xv3);
#pragma unroll
                    for (int r = 0; r < 8; r++) {
                        uint64_t wv2 =
                            *reinterpret_cast<const uint64_t*>(&ws[ci][tg * 8 + r][kh * 3 + kw]);
                        ffma2(acc[r][0], x01, wv2);
                        ffma2(acc[r][1], x23, wv2);
                    }
                }
            }
        }
        __syncthreads();
    }

    // ---- epilogue: demodulate + store ----
#pragma unroll
    for (int r = 0; r < 8; r++) {
        int co = co0 + tg * 8 + r;
        float d = g_decoef[b * COUT + co];
        size_t base = (((size_t)b * COUT + co) * H_ + (h0 + th)) * W_ + w0;
        float o0, o1, o2, o3;
        unpack2(acc[r][0], o0, o1);
        unpack2(acc[r][1], o2, o3);
        out[base + tw + 0]  = o0 * d;
        out[base + tw + 4]  = o1 * d;
        out[base + tw + 8]  = o2 * d;
        out[base + tw + 12] = o3 * d;
    }
}

// ---------------------------------------------------------------------------
extern "C" void kernel_launch(void* const* d_in, const int* in_sizes, int n_in,
                              void* d_out, int out_size) {
    const float* x      = (const float*)d_in[0];  // [16,128,128,128]
    const float* style  = (const float*)d_in[1];  // [16,512]
    const float* weight = (const float*)d_in[2];  // [1,128,128,3,3]
    const float* mod_w  = (const float*)d_in[3];  // [128,512]
    const float* mod_b  = (const float*)d_in[4];  // [128]
    float* out = (float*)d_out;                   // [16,128,128,128]

    k_style<<<B_, CIN>>>(style, mod_w, mod_b);
    k_w2<<<(COUT * CIN + 255) / 256, 256>>>(weight);
    k_decoef<<<(B_ * COUT + 255) / 256, 256>>>();

    dim3 grid(W_ / TW, H_ / TH, B_ * (COUT / TCO));  // 8 x 8 x 64
    k_conv<<<grid, 256>>>(x, weight, out);
}